// round 10
// baseline (speedup 1.0000x reference)
#include <cuda_runtime.h>
#include <cstdint>

#define N_NODES 128
#define F_IN    128
#define HID     64
#define N_CLS   40
#define NB      4
#define XPAD    132   // fp32 X rows
#define APAD    68    // packed A2 rows (u32)
#define WPAD    72    // packed W rows (u32)
#define YPAD    68    // fp32 Y rows

// Precomputed normalized adjacency and its square
__device__ float g_An[N_NODES * N_NODES];
__device__ float g_A2[N_NODES * N_NODES];

// ---------------------------------------------------------------------------
// helpers
// ---------------------------------------------------------------------------
__device__ __forceinline__ unsigned pack_split(float v0, float v1, unsigned& mid) {
    unsigned h;
    asm("cvt.rn.bf16x2.f32 %0, %1, %2;" : "=r"(h) : "f"(v1), "f"(v0)); // first src -> upper half
    float h0 = __uint_as_float(h << 16);
    float h1 = __uint_as_float(h & 0xffff0000u);
    float m0 = v0 - h0;
    float m1 = v1 - h1;
    asm("cvt.rn.bf16x2.f32 %0, %1, %2;" : "=r"(mid) : "f"(m1), "f"(m0));
    return h;
}

// Non-volatile: let ptxas schedule/pipeline HMMAs freely.
__device__ __forceinline__ void mma_bf16(float* c, const unsigned* a, unsigned b0, unsigned b1) {
    asm("mma.sync.aligned.m16n8k16.row.col.f32.bf16.bf16.f32 "
        "{%0,%1,%2,%3}, {%4,%5,%6,%7}, {%8,%9}, {%0,%1,%2,%3};"
        : "+f"(c[0]), "+f"(c[1]), "+f"(c[2]), "+f"(c[3])
        : "r"(a[0]), "r"(a[1]), "r"(a[2]), "r"(a[3]), "r"(b0), "r"(b1));
}

__device__ __forceinline__ void cp_async16(void* dst, const void* src) {
    unsigned d = (unsigned)__cvta_generic_to_shared(dst);
    asm volatile("cp.async.cg.shared.global [%0], [%1], 16;" :: "r"(d), "l"(src) : "memory");
}
__device__ __forceinline__ void cp_commit() { asm volatile("cp.async.commit_group;" ::: "memory"); }
__device__ __forceinline__ void cp_wait0()  { asm volatile("cp.async.wait_group 0;" ::: "memory"); }

// ---------------------------------------------------------------------------
// Kernel 0: build A_norm
// ---------------------------------------------------------------------------
__global__ void __launch_bounds__(1024, 1) build_anorm_kernel(const float* __restrict__ ew)
{
    __shared__ float dinv[N_NODES];
    const int tid = threadIdx.x;
    {
        const int row = tid >> 3, sub = tid & 7;
        float s = 0.f;
#pragma unroll
        for (int q = 0; q < 16; ++q) {
            int j = sub * 16 + q;
            int hi = row > j ? row : j, lo = row > j ? j : row;
            s += ew[hi * (hi + 1) / 2 + lo] + (j == row ? 1.f : 0.f);
        }
        s += __shfl_xor_sync(0xffffffffu, s, 1);
        s += __shfl_xor_sync(0xffffffffu, s, 2);
        s += __shfl_xor_sync(0xffffffffu, s, 4);
        if (sub == 0) dinv[row] = (s > 0.f) ? rsqrtf(s) : 0.f;
    }
    __syncthreads();
#pragma unroll
    for (int q = 0; q < 16; ++q) {
        int idx = tid + (q << 10);
        int i = idx >> 7, j = idx & 127;
        int hi = i > j ? i : j, lo = i > j ? j : i;
        float a = ew[hi * (hi + 1) / 2 + lo] + (j == i ? 1.f : 0.f);
        g_An[idx] = dinv[i] * a * dinv[j];
    }
}

// ---------------------------------------------------------------------------
// Kernel 1: A2 = A_norm @ A_norm
// ---------------------------------------------------------------------------
__global__ void compute_a2_kernel()
{
    __shared__ float rowi[N_NODES];
    const int i = blockIdx.x, j = threadIdx.x;
    rowi[j] = g_An[i * N_NODES + j];
    __syncthreads();
    float s = 0.f;
#pragma unroll 8
    for (int k = 0; k < N_NODES; ++k)
        s += rowi[k] * g_An[k * N_NODES + j];
    g_A2[i * N_NODES + j] = s;
}

// ---------------------------------------------------------------------------
// Main fused kernel: 512 threads / 16 warps, warp tile 16(M) x 32(N).
// bf16 split-emulated GEMMs (hh + hm + mh), m16n8k16, legacy mma.sync.
// 4 warps per SMSP so split/LDS prep of one warp overlaps HMMAs of others.
// ---------------------------------------------------------------------------
struct SMem {
    float    Xs[N_NODES][XPAD];     // fp32 X (cp.async dst)
    unsigned A2h[N_NODES][APAD];    // packed bf16x2 k-pairs, hi
    unsigned A2m[N_NODES][APAD];    // mid
    unsigned Wh[F_IN / 2][WPAD];    // packed bf16x2: (W[2kp][n], W[2kp+1][n]) hi
    unsigned Wm[F_IN / 2][WPAD];    // mid
    float    Ys[N_NODES][YPAD];     // fp32 Y = X@W
    float pooled[HID];
    float lb[HID];
    float cw[N_NODES];
};

__global__ void __launch_bounds__(512, 1)
dgcnn_main(const float* __restrict__ x,
           const float* __restrict__ lin_w,
           const float* __restrict__ lin_b,
           const float* __restrict__ conv_w,
           const float* __restrict__ conv_b,
           const float* __restrict__ fc_w,
           const float* __restrict__ fc_b,
           float* __restrict__ out,
           int Btot)
{
    extern __shared__ char smraw[];
    SMem* sm = reinterpret_cast<SMem*>(smraw);

    const int tid  = threadIdx.x;
    const int lane = tid & 31;
    const int warp = tid >> 5;
    const int g    = lane >> 2;   // 0..7
    const int tg   = lane & 3;    // 0..3
    const int wM   = warp & 7;    // 0..7 : 16 rows each
    const int wN   = warp >> 3;   // 0..1 : 32 cols each
    const int bbase = blockIdx.x * NB;

    // ---- prefetch first X (async): 4096 16B chunks, 8 per thread ----
    if (bbase < Btot) {
        const float* xb = x + (size_t)bbase * (N_NODES * F_IN);
#pragma unroll
        for (int c = 0; c < 8; ++c) {
            int i4 = tid + (c << 9);
            int r  = i4 >> 5;
            int cc = (i4 & 31) << 2;
            cp_async16(&sm->Xs[r][cc], xb + r * F_IN + cc);
        }
        cp_commit();
    }

    // ---- pre-split A2 (8192 pairs, 16 per thread) ----
#pragma unroll
    for (int q = 0; q < 16; ++q) {
        int p = tid + (q << 9);
        int r = p >> 6, c = p & 63;
        float2 v = *reinterpret_cast<const float2*>(g_A2 + r * N_NODES + 2 * c);
        unsigned m, h = pack_split(v.x, v.y, m);
        sm->A2h[r][c] = h;
        sm->A2m[r][c] = m;
    }
    // ---- pre-split W (4096 pairs, 8 per thread) ----
#pragma unroll
    for (int q = 0; q < 8; ++q) {
        int p = tid + (q << 9);
        int kp = p >> 6, n = p & 63;
        float v0 = lin_w[(2 * kp) * HID + n];
        float v1 = lin_w[(2 * kp + 1) * HID + n];
        unsigned m, h = pack_split(v0, v1, m);
        sm->Wh[kp][n] = h;
        sm->Wm[kp][n] = m;
    }
    if (tid < HID)     sm->lb[tid] = lin_b[tid];
    if (tid < N_NODES) sm->cw[tid] = conv_w[tid];

#pragma unroll 1
    for (int it = 0; it < NB; ++it) {
        const int b = bbase + it;
        if (b >= Btot) break;

        cp_wait0();
        __syncthreads();                       // Xs ready; prologue/prev-iter done
        if (tid < HID) sm->pooled[tid] = 0.f;

        float acc[4][4];

        // ============ GEMM1: Y = X @ W  (bf16 split, X inline) ==============
#pragma unroll
        for (int nt = 0; nt < 4; ++nt)
#pragma unroll
            for (int j = 0; j < 4; ++j) acc[nt][j] = 0.f;

#pragma unroll
        for (int kk = 0; kk < 8; ++kk) {
            unsigned ah[4], am[4], bh[4][2], bm[4][2];
            {
                const float* xr = &sm->Xs[wM * 16 + g][16 * kk + 2 * tg];
                float2 v0 = *reinterpret_cast<const float2*>(xr);
                float2 v1 = *reinterpret_cast<const float2*>(xr + 8 * XPAD);
                float2 v2 = *reinterpret_cast<const float2*>(xr + 8);
                float2 v3 = *reinterpret_cast<const float2*>(xr + 8 * XPAD + 8);
                ah[0] = pack_split(v0.x, v0.y, am[0]);
                ah[1] = pack_split(v1.x, v1.y, am[1]);
                ah[2] = pack_split(v2.x, v2.y, am[2]);
                ah[3] = pack_split(v3.x, v3.y, am[3]);
            }
#pragma unroll
            for (int nt = 0; nt < 4; ++nt) {
                int n  = wN * 32 + nt * 8 + g;
                int kp = 8 * kk + tg;
                bh[nt][0] = sm->Wh[kp][n];     bm[nt][0] = sm->Wm[kp][n];
                bh[nt][1] = sm->Wh[kp + 4][n]; bm[nt][1] = sm->Wm[kp + 4][n];
            }
            // pass 1: hi*hi
#pragma unroll
            for (int nt = 0; nt < 4; ++nt)
                mma_bf16(acc[nt], ah, bh[nt][0], bh[nt][1]);
            // pass 2: hi*mid
#pragma unroll
            for (int nt = 0; nt < 4; ++nt)
                mma_bf16(acc[nt], ah, bm[nt][0], bm[nt][1]);
            // pass 3: mid*hi
#pragma unroll
            for (int nt = 0; nt < 4; ++nt)
                mma_bf16(acc[nt], am, bh[nt][0], bh[nt][1]);
        }
        __syncthreads();                       // all warps done reading Xs

        // ---- store Y (fp32) ----
        {
            int r = wM * 16 + g;
#pragma unroll
            for (int nt = 0; nt < 4; ++nt) {
                int cc = wN * 32 + nt * 8 + 2 * tg;
                float2 v;
                v.x = acc[nt][0]; v.y = acc[nt][1];
                *reinterpret_cast<float2*>(&sm->Ys[r][cc]) = v;
                v.x = acc[nt][2]; v.y = acc[nt][3];
                *reinterpret_cast<float2*>(&sm->Ys[r + 8][cc]) = v;
            }
        }
        __syncthreads();                       // Ys visible

        // ---- prefetch next batch X while GEMM2 runs ----
        if (it + 1 < NB && b + 1 < Btot) {
            const float* xb = x + (size_t)(b + 1) * (N_NODES * F_IN);
#pragma unroll
            for (int c = 0; c < 8; ++c) {
                int i4 = tid + (c << 9);
                int r  = i4 >> 5;
                int cc = (i4 & 31) << 2;
                cp_async16(&sm->Xs[r][cc], xb + r * F_IN + cc);
            }
            cp_commit();
        }

        // ============ GEMM2: Z = A2 @ Y  (A2 pre-split, Y inline) ===========
#pragma unroll
        for (int nt = 0; nt < 4; ++nt)
#pragma unroll
            for (int j = 0; j < 4; ++j) acc[nt][j] = 0.f;

#pragma unroll
        for (int kk = 0; kk < 8; ++kk) {
            unsigned ah[4], am[4], bh[4][2], bm[4][2];
            {
                int row = wM * 16 + g;
                int kp  = 8 * kk + tg;
                ah[0] = sm->A2h[row][kp];         am[0] = sm->A2m[row][kp];
                ah[1] = sm->A2h[row + 8][kp];     am[1] = sm->A2m[row + 8][kp];
                ah[2] = sm->A2h[row][kp + 4];     am[2] = sm->A2m[row][kp + 4];
                ah[3] = sm->A2h[row + 8][kp + 4]; am[3] = sm->A2m[row + 8][kp + 4];
            }
#pragma unroll
            for (int nt = 0; nt < 4; ++nt) {
                int n  = wN * 32 + nt * 8 + g;
                int r0 = 16 * kk + 2 * tg;
                bh[nt][0] = pack_split(sm->Ys[r0][n],     sm->Ys[r0 + 1][n], bm[nt][0]);
                bh[nt][1] = pack_split(sm->Ys[r0 + 8][n], sm->Ys[r0 + 9][n], bm[nt][1]);
            }
#pragma unroll
            for (int nt = 0; nt < 4; ++nt)
                mma_bf16(acc[nt], ah, bh[nt][0], bh[nt][1]);
#pragma unroll
            for (int nt = 0; nt < 4; ++nt)
                mma_bf16(acc[nt], ah, bm[nt][0], bm[nt][1]);
#pragma unroll
            for (int nt = 0; nt < 4; ++nt)
                mma_bf16(acc[nt], am, bh[nt][0], bh[nt][1]);
        }

        // ================= epilogue: bias+relu, conv_w pooling ===============
        float p[8];
#pragma unroll
        for (int i = 0; i < 8; ++i) p[i] = 0.f;
        {
            int r = wM * 16 + g;
            float c0 = sm->cw[r], c1 = sm->cw[r + 8];
#pragma unroll
            for (int nt = 0; nt < 4; ++nt) {
                int cc = wN * 32 + nt * 8 + 2 * tg;
                float l0 = sm->lb[cc], l1 = sm->lb[cc + 1];
                p[2 * nt]     += fmaxf(acc[nt][0] + l0, 0.f) * c0
                               + fmaxf(acc[nt][2] + l0, 0.f) * c1;
                p[2 * nt + 1] += fmaxf(acc[nt][1] + l1, 0.f) * c0
                               + fmaxf(acc[nt][3] + l1, 0.f) * c1;
            }
        }
#pragma unroll
        for (int i = 0; i < 8; ++i) {
            p[i] += __shfl_xor_sync(0xffffffffu, p[i], 4);
            p[i] += __shfl_xor_sync(0xffffffffu, p[i], 8);
            p[i] += __shfl_xor_sync(0xffffffffu, p[i], 16);
        }
        if (lane < 4) {
#pragma unroll
            for (int nt = 0; nt < 4; ++nt) {
                atomicAdd(&sm->pooled[wN * 32 + nt * 8 + 2 * lane],     p[2 * nt]);
                atomicAdd(&sm->pooled[wN * 32 + nt * 8 + 2 * lane + 1], p[2 * nt + 1]);
            }
        }
        __syncthreads();                       // pooled complete

        // ---- relu(+conv_b), FC 64->40, write out ----
        if (tid < N_CLS) {
            float cb = conv_b[0];
            float o = fc_b[tid];
#pragma unroll
            for (int h = 0; h < HID; ++h) {
                float ph = fmaxf(sm->pooled[h] + cb, 0.f);
                o += ph * __ldg(fc_w + h * N_CLS + tid);
            }
            out[(size_t)b * N_CLS + tid] = o;
        }
    }
}

// ---------------------------------------------------------------------------
extern "C" void kernel_launch(void* const* d_in, const int* in_sizes, int n_in,
                              void* d_out, int out_size)
{
    const float* x   = (const float*)d_in[0];
    const float* ew  = (const float*)d_in[1];
    const float* lw  = (const float*)d_in[2];
    const float* lb  = (const float*)d_in[3];
    const float* cw  = (const float*)d_in[4];
    const float* cb  = (const float*)d_in[5];
    const float* fw  = (const float*)d_in[6];
    const float* fb  = (const float*)d_in[7];
    float* outp      = (float*)d_out;

    const int Btot = in_sizes[0] / (N_NODES * F_IN);

    build_anorm_kernel<<<1, 1024>>>(ew);
    compute_a2_kernel<<<N_NODES, N_NODES>>>();

    cudaFuncSetAttribute(dgcnn_main, cudaFuncAttributeMaxDynamicSharedMemorySize,
                         (int)sizeof(SMem));
    const int grid = (Btot + NB - 1) / NB;
    dgcnn_main<<<grid, 512, sizeof(SMem)>>>(x, lw, lb, cw, cb, fw, fb, outp, Btot);
}

// round 15
// speedup vs baseline: 1.0738x; 1.0738x over previous
#include <cuda_runtime.h>
#include <cstdint>

#define N_NODES 128
#define F_IN    128
#define HID     64
#define N_CLS   40
#define NB      4
#define XPAD    68    // packed u32 rows: 4-bank shift -> conflict-free frag LDS.32
#define APAD    68
#define WPAD    72
#define YPAD    68

// Precomputed A_norm^2 (scratch)
__device__ float g_A2[N_NODES * N_NODES];

// ---------------------------------------------------------------------------
// helpers
// ---------------------------------------------------------------------------
__device__ __forceinline__ unsigned pack_split(float v0, float v1, unsigned& mid) {
    unsigned h;
    asm("cvt.rn.bf16x2.f32 %0, %1, %2;" : "=r"(h) : "f"(v1), "f"(v0)); // first src -> upper half
    float h0 = __uint_as_float(h << 16);
    float h1 = __uint_as_float(h & 0xffff0000u);
    float m0 = v0 - h0;
    float m1 = v1 - h1;
    asm("cvt.rn.bf16x2.f32 %0, %1, %2;" : "=r"(mid) : "f"(m1), "f"(m0));
    return h;
}

// Non-volatile: let ptxas schedule/pipeline HMMAs freely.
__device__ __forceinline__ void mma_bf16(float* c, const unsigned* a, unsigned b0, unsigned b1) {
    asm("mma.sync.aligned.m16n8k16.row.col.f32.bf16.bf16.f32 "
        "{%0,%1,%2,%3}, {%4,%5,%6,%7}, {%8,%9}, {%0,%1,%2,%3};"
        : "+f"(c[0]), "+f"(c[1]), "+f"(c[2]), "+f"(c[3])
        : "r"(a[0]), "r"(a[1]), "r"(a[2]), "r"(a[3]), "r"(b0), "r"(b1));
}

__device__ __forceinline__ int tril_idx(int i, int j) {
    int hi = i > j ? i : j;
    int lo = i > j ? j : i;
    return hi * (hi + 1) / 2 + lo;
}

// ---------------------------------------------------------------------------
// Fused prologue kernel: A2 = (D^-1/2 (A+I) D^-1/2)^2, 128 blocks x 128 thr.
// Each block redundantly computes dinv (L2-hot tril reads), then its A2 row.
// ---------------------------------------------------------------------------
__global__ void __launch_bounds__(128, 8) build_a2_kernel(const float* __restrict__ ew)
{
    __shared__ float dinv[N_NODES];
    __shared__ float rowi[N_NODES];
    const int i = blockIdx.x;
    const int j = threadIdx.x;

    float s = 0.f;
#pragma unroll 8
    for (int k = 0; k < N_NODES; ++k)
        s += ew[tril_idx(j, k)] + (k == j ? 1.f : 0.f);
    dinv[j] = (s > 0.f) ? rsqrtf(s) : 0.f;
    __syncthreads();

    rowi[j] = dinv[i] * (ew[tril_idx(i, j)] + (i == j ? 1.f : 0.f)) * dinv[j];
    __syncthreads();

    const float dj = dinv[j];
    float acc = 0.f;
#pragma unroll 8
    for (int k = 0; k < N_NODES; ++k) {
        float akj = dinv[k] * (ew[tril_idx(k, j)] + (k == j ? 1.f : 0.f)) * dj;
        acc += rowi[k] * akj;
    }
    g_A2[i * N_NODES + j] = acc;
}

// ---------------------------------------------------------------------------
// Main fused kernel: 256 threads / 8 warps, warp tile 32(M) x 32(N).
// bf16 split-emulated GEMMs (hh+hm+mh). All scalar phases hidden under GEMMs:
//  - X(it+1): LDG at GEMM1(it) start; split->smem interleaved into GEMM2(it).
//  - FC(it-1): warps 0-1 at head of GEMM1(it) (co-warps keep tensor pipe fed).
//  - 2 syncthreads per batch.
// ---------------------------------------------------------------------------
struct SMem {
    unsigned Xh[N_NODES][XPAD];     // packed bf16x2 k-pairs of X, hi
    unsigned Xm[N_NODES][XPAD];     // mid
    unsigned A2h[N_NODES][APAD];
    unsigned A2m[N_NODES][APAD];
    unsigned Wh[F_IN / 2][WPAD];    // (W[2kp][n], W[2kp+1][n]) packed
    unsigned Wm[F_IN / 2][WPAD];
    float    Ys[N_NODES][YPAD];     // fp32 Y = X@W
    float pooled[2][HID];           // double-buffered (FC deferred one batch)
    float lb[HID];
    float cw[N_NODES];
};

__global__ void __launch_bounds__(256, 1)
dgcnn_main(const float* __restrict__ x,
           const float* __restrict__ lin_w,
           const float* __restrict__ lin_b,
           const float* __restrict__ conv_w,
           const float* __restrict__ conv_b,
           const float* __restrict__ fc_w,
           const float* __restrict__ fc_b,
           float* __restrict__ out,
           int Btot)
{
    extern __shared__ char smraw[];
    SMem* sm = reinterpret_cast<SMem*>(smraw);

    const int tid  = threadIdx.x;
    const int lane = tid & 31;
    const int warp = tid >> 5;
    const int g    = lane >> 2;
    const int tg   = lane & 3;
    const int wM   = warp >> 1;   // 0..3
    const int wN   = warp & 1;    // 0..1
    const int bbase = blockIdx.x * NB;

    // ---- prologue: pre-split A2 and W ----
#pragma unroll
    for (int q = 0; q < 32; ++q) {
        int p = tid + (q << 8);
        int r = p >> 6, c = p & 63;
        float2 v = *reinterpret_cast<const float2*>(g_A2 + r * N_NODES + 2 * c);
        unsigned m, h = pack_split(v.x, v.y, m);
        sm->A2h[r][c] = h;
        sm->A2m[r][c] = m;
    }
#pragma unroll
    for (int q = 0; q < 16; ++q) {
        int p = tid + (q << 8);
        int kp = p >> 6, n = p & 63;
        float v0 = lin_w[(2 * kp) * HID + n];
        float v1 = lin_w[(2 * kp + 1) * HID + n];
        unsigned m, h = pack_split(v0, v1, m);
        sm->Wh[kp][n] = h;
        sm->Wm[kp][n] = m;
    }
    if (tid < HID)     sm->lb[tid] = lin_b[tid];
    if (tid < N_NODES) sm->cw[tid] = conv_w[tid];
    if (tid < 2 * HID) sm->pooled[tid >> 6][tid & 63] = 0.f;

    // ---- prologue: load + split X(0) ----
    uint4 xr[16];
    if (bbase < Btot) {
        const uint4* xb = (const uint4*)(x + (size_t)bbase * (N_NODES * F_IN));
#pragma unroll
        for (int c = 0; c < 16; ++c) xr[c] = __ldg(xb + (c << 8) + tid);
#pragma unroll
        for (int c = 0; c < 16; ++c) {
            int i4 = tid + (c << 8);
            int r = i4 >> 5, kp = (i4 & 31) << 1;
            float4 v = *(float4*)&xr[c];
            unsigned m0, m1;
            unsigned h0 = pack_split(v.x, v.y, m0);
            unsigned h1 = pack_split(v.z, v.w, m1);
            *(uint2*)&sm->Xh[r][kp] = make_uint2(h0, h1);
            *(uint2*)&sm->Xm[r][kp] = make_uint2(m0, m1);
        }
    }
    __syncthreads();

#pragma unroll 1
    for (int it = 0; it < NB; ++it) {
        const int b = bbase + it;
        if (b >= Btot) break;
        const bool haveNext = (it + 1 < NB) && (b + 1 < Btot);

        // ---- issue LDG for X(it+1); arrives well before GEMM2's split ----
        if (haveNext) {
            const uint4* xb = (const uint4*)(x + (size_t)(b + 1) * (N_NODES * F_IN));
#pragma unroll
            for (int c = 0; c < 16; ++c) xr[c] = __ldg(xb + (c << 8) + tid);
        }

        // ---- deferred FC(it-1): warps 0-1; tensor pipe fed by co-warps ----
        if (it > 0 && tid < N_CLS) {
            const float* pl = sm->pooled[(it - 1) & 1];
            float cb = conv_b[0];
            float o = fc_b[tid];
#pragma unroll
            for (int h = 0; h < HID; ++h) {
                float ph = fmaxf(pl[h] + cb, 0.f);
                o += ph * __ldg(fc_w + h * N_CLS + tid);
            }
            out[(size_t)(b - 1) * N_CLS + tid] = o;
        }
        // zero this batch's pool buffer (distinct from the one FC reads)
        if (tid < HID) sm->pooled[it & 1][tid] = 0.f;

        float acc[2][4][4];

        // ============ GEMM1: Y = X @ W  (pre-split X, frag LDS.32) ==========
#pragma unroll
        for (int mt = 0; mt < 2; ++mt)
#pragma unroll
            for (int nt = 0; nt < 4; ++nt)
#pragma unroll
                for (int j = 0; j < 4; ++j) acc[mt][nt][j] = 0.f;

#pragma unroll
        for (int kk = 0; kk < 8; ++kk) {
            unsigned ah[2][4], am[2][4], bh[4][2], bm[4][2];
            const int kp = 8 * kk + tg;
#pragma unroll
            for (int mt = 0; mt < 2; ++mt) {
                int row = wM * 32 + mt * 16 + g;
                ah[mt][0] = sm->Xh[row][kp];         am[mt][0] = sm->Xm[row][kp];
                ah[mt][1] = sm->Xh[row + 8][kp];     am[mt][1] = sm->Xm[row + 8][kp];
                ah[mt][2] = sm->Xh[row][kp + 4];     am[mt][2] = sm->Xm[row][kp + 4];
                ah[mt][3] = sm->Xh[row + 8][kp + 4]; am[mt][3] = sm->Xm[row + 8][kp + 4];
            }
#pragma unroll
            for (int nt = 0; nt < 4; ++nt) {
                int n = wN * 32 + nt * 8 + g;
                bh[nt][0] = sm->Wh[kp][n];     bm[nt][0] = sm->Wm[kp][n];
                bh[nt][1] = sm->Wh[kp + 4][n]; bm[nt][1] = sm->Wm[kp + 4][n];
            }
#pragma unroll
            for (int nt = 0; nt < 4; ++nt) {
                mma_bf16(acc[0][nt], ah[0], bh[nt][0], bh[nt][1]);
                mma_bf16(acc[1][nt], ah[1], bh[nt][0], bh[nt][1]);
            }
#pragma unroll
            for (int nt = 0; nt < 4; ++nt) {
                mma_bf16(acc[0][nt], ah[0], bm[nt][0], bm[nt][1]);
                mma_bf16(acc[1][nt], ah[1], bm[nt][0], bm[nt][1]);
            }
#pragma unroll
            for (int nt = 0; nt < 4; ++nt) {
                mma_bf16(acc[0][nt], am[0], bh[nt][0], bh[nt][1]);
                mma_bf16(acc[1][nt], am[1], bh[nt][0], bh[nt][1]);
            }
        }

        // ---- store Y (fp32) straight from accumulators ----
#pragma unroll
        for (int mt = 0; mt < 2; ++mt) {
            int r = wM * 32 + mt * 16 + g;
#pragma unroll
            for (int nt = 0; nt < 4; ++nt) {
                int cc = wN * 32 + nt * 8 + 2 * tg;
                *reinterpret_cast<float2*>(&sm->Ys[r][cc])     = make_float2(acc[mt][nt][0], acc[mt][nt][1]);
                *reinterpret_cast<float2*>(&sm->Ys[r + 8][cc]) = make_float2(acc[mt][nt][2], acc[mt][nt][3]);
            }
        }
        __syncthreads();            // Ys ready; Xs(it) free for overwrite

        // ============ GEMM2: Z = A2 @ Y, with X(it+1) split interleaved ======
#pragma unroll
        for (int mt = 0; mt < 2; ++mt)
#pragma unroll
            for (int nt = 0; nt < 4; ++nt)
#pragma unroll
                for (int j = 0; j < 4; ++j) acc[mt][nt][j] = 0.f;

#pragma unroll
        for (int kk = 0; kk < 8; ++kk) {
            // hide X(it+1) split under tensor work: 2 chunks per kk
            if (haveNext) {
#pragma unroll
                for (int cc2 = 0; cc2 < 2; ++cc2) {
                    int c = 2 * kk + cc2;
                    int i4 = tid + (c << 8);
                    int r = i4 >> 5, kp2 = (i4 & 31) << 1;
                    float4 v = *(float4*)&xr[c];
                    unsigned m0, m1;
                    unsigned h0 = pack_split(v.x, v.y, m0);
                    unsigned h1 = pack_split(v.z, v.w, m1);
                    *(uint2*)&sm->Xh[r][kp2] = make_uint2(h0, h1);
                    *(uint2*)&sm->Xm[r][kp2] = make_uint2(m0, m1);
                }
            }
            unsigned ah[2][4], am[2][4], bh[4][2], bm[4][2];
            const int kp = 8 * kk + tg;
#pragma unroll
            for (int mt = 0; mt < 2; ++mt) {
                int row = wM * 32 + mt * 16 + g;
                ah[mt][0] = sm->A2h[row][kp];         am[mt][0] = sm->A2m[row][kp];
                ah[mt][1] = sm->A2h[row + 8][kp];     am[mt][1] = sm->A2m[row + 8][kp];
                ah[mt][2] = sm->A2h[row][kp + 4];     am[mt][2] = sm->A2m[row][kp + 4];
                ah[mt][3] = sm->A2h[row + 8][kp + 4]; am[mt][3] = sm->A2m[row + 8][kp + 4];
            }
#pragma unroll
            for (int nt = 0; nt < 4; ++nt) {
                int n  = wN * 32 + nt * 8 + g;
                int r0 = 16 * kk + 2 * tg;
                bh[nt][0] = pack_split(sm->Ys[r0][n],     sm->Ys[r0 + 1][n], bm[nt][0]);
                bh[nt][1] = pack_split(sm->Ys[r0 + 8][n], sm->Ys[r0 + 9][n], bm[nt][1]);
            }
#pragma unroll
            for (int nt = 0; nt < 4; ++nt) {
                mma_bf16(acc[0][nt], ah[0], bh[nt][0], bh[nt][1]);
                mma_bf16(acc[1][nt], ah[1], bh[nt][0], bh[nt][1]);
            }
#pragma unroll
            for (int nt = 0; nt < 4; ++nt) {
                mma_bf16(acc[0][nt], ah[0], bm[nt][0], bm[nt][1]);
                mma_bf16(acc[1][nt], ah[1], bm[nt][0], bm[nt][1]);
            }
#pragma unroll
            for (int nt = 0; nt < 4; ++nt) {
                mma_bf16(acc[0][nt], am[0], bh[nt][0], bh[nt][1]);
                mma_bf16(acc[1][nt], am[1], bh[nt][0], bh[nt][1]);
            }
        }

        // ================= epilogue: bias+relu, conv_w pooling ===============
        float p[8];
#pragma unroll
        for (int i = 0; i < 8; ++i) p[i] = 0.f;
#pragma unroll
        for (int mt = 0; mt < 2; ++mt) {
            int r = wM * 32 + mt * 16 + g;
            float c0 = sm->cw[r], c1 = sm->cw[r + 8];
#pragma unroll
            for (int nt = 0; nt < 4; ++nt) {
                int cc = wN * 32 + nt * 8 + 2 * tg;
                float l0 = sm->lb[cc], l1 = sm->lb[cc + 1];
                p[2 * nt]     += fmaxf(acc[mt][nt][0] + l0, 0.f) * c0
                               + fmaxf(acc[mt][nt][2] + l0, 0.f) * c1;
                p[2 * nt + 1] += fmaxf(acc[mt][nt][1] + l1, 0.f) * c0
                               + fmaxf(acc[mt][nt][3] + l1, 0.f) * c1;
            }
        }
#pragma unroll
        for (int i = 0; i < 8; ++i) {
            p[i] += __shfl_xor_sync(0xffffffffu, p[i], 4);
            p[i] += __shfl_xor_sync(0xffffffffu, p[i], 8);
            p[i] += __shfl_xor_sync(0xffffffffu, p[i], 16);
        }
        if (lane < 4) {
            float* pl = sm->pooled[it & 1];
#pragma unroll
            for (int nt = 0; nt < 4; ++nt) {
                atomicAdd(&pl[wN * 32 + nt * 8 + 2 * lane],     p[2 * nt]);
                atomicAdd(&pl[wN * 32 + nt * 8 + 2 * lane + 1], p[2 * nt + 1]);
            }
        }
        __syncthreads();            // pooled(it) done; Xs(it+1) ready
    }

    // ---- tail FC for the last batch ----
    {
        int nb_done = min(NB, Btot - bbase);
        if (nb_done > 0 && tid < N_CLS) {
            int itl = nb_done - 1;
            const float* pl = sm->pooled[itl & 1];
            float cb = conv_b[0];
            float o = fc_b[tid];
#pragma unroll
            for (int h = 0; h < HID; ++h) {
                float ph = fmaxf(pl[h] + cb, 0.f);
                o += ph * __ldg(fc_w + h * N_CLS + tid);
            }
            out[(size_t)(bbase + itl) * N_CLS + tid] = o;
        }
    }
}

// ---------------------------------------------------------------------------
extern "C" void kernel_launch(void* const* d_in, const int* in_sizes, int n_in,
                              void* d_out, int out_size)
{
    const float* x   = (const float*)d_in[0];
    const float* ew  = (const float*)d_in[1];
    const float* lw  = (const float*)d_in[2];
    const float* lb  = (const float*)d_in[3];
    const float* cw  = (const float*)d_in[4];
    const float* cb  = (const float*)d_in[5];
    const float* fw  = (const float*)d_in[6];
    const float* fb  = (const float*)d_in[7];
    float* outp      = (float*)d_out;

    const int Btot = in_sizes[0] / (N_NODES * F_IN);

    build_a2_kernel<<<N_NODES, N_NODES>>>(ew);

    cudaFuncSetAttribute(dgcnn_main, cudaFuncAttributeMaxDynamicSharedMemorySize,
                         (int)sizeof(SMem));
    const int grid = (Btot + NB - 1) / NB;
    dgcnn_main<<<grid, 256, sizeof(SMem)>>>(x, lw, lb, cw, cb, fw, fb, outp, Btot);
}